// round 1
// baseline (speedup 1.0000x reference)
#include <cuda_runtime.h>
#include <cuda_bf16.h>
#include <math.h>

// Problem constants (fixed bench shapes)
#define BH    32            // B*H = 4*8
#define LSEQ  2048          // sequence length
#define DIM   64            // head dim
#define USEL  40            // u = U_part = 5*ceil(ln(2048)) = 40
#define NCH   8             // key chunks for split-softmax attention
#define CHK   (LSEQ/NCH)    // 256 keys per chunk

// -------- scratch (device globals; no allocation allowed) --------
__device__ float g_M[BH * LSEQ];                    // sparsity scores
__device__ int   g_topk[BH * USEL];                 // selected query indices
__device__ float g_meanV[BH * DIM];                 // per-(b,h) mean of V
__device__ float g_pm[BH * NCH * USEL];             // partial softmax max
__device__ float g_pl[BH * NCH * USEL];             // partial softmax denom
__device__ float g_pacc[(size_t)BH * NCH * USEL * DIM]; // partial outputs (2.6 MB)

// ================= 1. mean of V per (b,h) =================
__global__ void mean_kernel(const float* __restrict__ V) {
    __shared__ float sb[256];
    int bh = blockIdx.x, t = threadIdx.x;
    int d = t & 63, part = t >> 6;
    const float* Vb = V + (size_t)bh * LSEQ * DIM;
    float s = 0.f;
    for (int l = part; l < LSEQ; l += 4)
        s += Vb[(size_t)l * DIM + d];
    sb[t] = s;
    __syncthreads();
    if (t < 64)
        g_meanV[bh * DIM + t] =
            (sb[t] + sb[t + 64] + sb[t + 128] + sb[t + 192]) * (1.0f / LSEQ);
}

// ================= 2. broadcast-fill output with meanV =================
__global__ void fill_kernel(float4* __restrict__ out) {
    int i = blockIdx.x * blockDim.x + threadIdx.x;   // over BH*LSEQ*16 float4s
    int bh = i >> 15;                                // LSEQ*16 = 32768
    int d4 = i & 15;
    out[i] = ((const float4*)g_meanV)[bh * 16 + d4];
}

// ================= 3. M scores (sampled QK gather) =================
// one warp per (bh, q); lane holds q[lane], q[lane+32]
__global__ void m_kernel(const float* __restrict__ Q,
                         const float* __restrict__ K,
                         const int* __restrict__ idxs, int u) {
    int w = blockIdx.x * 8 + (threadIdx.x >> 5);
    int lane = threadIdx.x & 31;
    int bh = w >> 11;
    int q  = w & (LSEQ - 1);

    const float* Qr = Q + ((size_t)bh * LSEQ + q) * DIM;
    float q0 = Qr[lane], q1 = Qr[lane + 32];
    const int* ip = idxs + (size_t)q * u;
    const float* Kb = K + (size_t)bh * LSEQ * DIM;

    float mx = -1e30f, sm = 0.f;
    for (int s = 0; s < u; s++) {
        int ki = __ldg(ip + s);
        const float* Kr = Kb + (size_t)ki * DIM;
        float d = q0 * __ldg(Kr + lane) + q1 * __ldg(Kr + lane + 32);
        d += __shfl_xor_sync(0xFFFFFFFFu, d, 16);
        d += __shfl_xor_sync(0xFFFFFFFFu, d, 8);
        d += __shfl_xor_sync(0xFFFFFFFFu, d, 4);
        d += __shfl_xor_sync(0xFFFFFFFFu, d, 2);
        d += __shfl_xor_sync(0xFFFFFFFFu, d, 1);
        mx = fmaxf(mx, d);
        sm += d;
    }
    if (lane == 0)
        g_M[bh * LSEQ + q] = mx - sm * (1.0f / LSEQ);
}

// ================= 4. top-40 per (b,h), iterative block argmax =================
__global__ void topk_kernel() {
    __shared__ float sv[LSEQ];
    __shared__ float rv[256];
    __shared__ int   ri[256];
    int bh = blockIdx.x, t = threadIdx.x;
    for (int i = t; i < LSEQ; i += 256)
        sv[i] = g_M[bh * LSEQ + i];
    __syncthreads();

    for (int it = 0; it < USEL; it++) {
        float bv = -1e38f; int bi = LSEQ;
        for (int i = t; i < LSEQ; i += 256) {
            float v = sv[i];
            if (v > bv) { bv = v; bi = i; }   // ascending i => smallest index kept on tie
        }
        rv[t] = bv; ri[t] = bi;
        __syncthreads();
        for (int s = 128; s > 0; s >>= 1) {
            if (t < s) {
                float ov = rv[t + s]; int oi = ri[t + s];
                if (ov > rv[t] || (ov == rv[t] && oi < ri[t])) { rv[t] = ov; ri[t] = oi; }
            }
            __syncthreads();
        }
        if (t == 0) {
            g_topk[bh * USEL + it] = ri[0];
            sv[ri[0]] = -1e38f;
        }
        __syncthreads();
    }
}

// ================= 5. attention partials: block = (key-chunk, bh) =================
// 256 threads: i = t>>5 (0..7), j = t&31. Thread owns queries {i+8a} (a=0..4),
// keys/dims {j, j+32}. Flash-style online softmax over 4 tiles of 64 keys.
__global__ __launch_bounds__(256) void attn_kernel(const float* __restrict__ Q,
                                                   const float* __restrict__ K,
                                                   const float* __restrict__ V) {
    __shared__ float Qs[USEL * DIM];     // 10.0 KB (pre-scaled Q)
    __shared__ float KV[64 * 65];        // 16.25 KB (K tile, then V tile)
    __shared__ float Pt[USEL * 64];      // 10.0 KB (scores -> probs)
    __shared__ float s_m[USEL], s_l[USEL], s_f[USEL], s_tm[USEL];

    int ch = blockIdx.x, bh = blockIdx.y;
    int t = threadIdx.x;
    int i = t >> 5, j = t & 31;

    const float* Kb = K + (size_t)bh * LSEQ * DIM;
    const float* Vb = V + (size_t)bh * LSEQ * DIM;

    // stage selected Q rows, pre-scaled by 1/sqrt(D)
    for (int e = t; e < USEL * DIM; e += 256) {
        int q = e >> 6, d = e & 63;
        int qi = g_topk[bh * USEL + q];
        Qs[e] = Q[((size_t)bh * LSEQ + qi) * DIM + d] * 0.125f;
    }
    if (t < USEL) { s_m[t] = -1e30f; s_l[t] = 0.f; }
    float acc[5][2];
#pragma unroll
    for (int a = 0; a < 5; a++) { acc[a][0] = 0.f; acc[a][1] = 0.f; }
    __syncthreads();

    int kbase0 = ch * CHK;
    for (int kt = 0; kt < CHK / 64; kt++) {
        int kb = kbase0 + kt * 64;

        // --- stage K tile (padded rows, stride 65) ---
        for (int e = t; e < 64 * 64; e += 256) {
            int r = e >> 6, c = e & 63;
            KV[r * 65 + c] = Kb[(size_t)(kb + r) * DIM + c];
        }
        __syncthreads();                                   // (A)

        // --- S = Qs @ K^T ---
        float s[5][2];
#pragma unroll
        for (int a = 0; a < 5; a++) { s[a][0] = 0.f; s[a][1] = 0.f; }
        for (int d = 0; d < 64; d++) {
            float k0 = KV[j * 65 + d];
            float k1 = KV[(j + 32) * 65 + d];
#pragma unroll
            for (int a = 0; a < 5; a++) {
                float qv = Qs[(i + 8 * a) * 64 + d];
                s[a][0] = fmaf(qv, k0, s[a][0]);
                s[a][1] = fmaf(qv, k1, s[a][1]);
            }
        }
#pragma unroll
        for (int a = 0; a < 5; a++) {
            Pt[(i + 8 * a) * 64 + j]      = s[a][0];
            Pt[(i + 8 * a) * 64 + j + 32] = s[a][1];
        }
        __syncthreads();                                   // (B)

        // tile max + rescale factor (one thread per query), V staged in parallel
        if (t < USEL) {
            float tm = -1e30f;
            for (int k = 0; k < 64; k++) tm = fmaxf(tm, Pt[t * 64 + k]);
            float mo = s_m[t];
            float mn = fmaxf(mo, tm);
            s_tm[t] = mn;
            s_f[t]  = __expf(mo - mn);
            s_m[t]  = mn;
        }
        for (int e = t; e < 64 * 64; e += 256) {           // stage V over K buffer
            int r = e >> 6, c = e & 63;
            KV[r * 65 + c] = Vb[(size_t)(kb + r) * DIM + c];
        }
        __syncthreads();                                   // (C)

        // exponentiate scores; rescale accumulators
        for (int e = t; e < USEL * 64; e += 256) {
            int q = e >> 6;
            Pt[e] = __expf(Pt[e] - s_tm[q]);
        }
#pragma unroll
        for (int a = 0; a < 5; a++) {
            float f = s_f[i + 8 * a];
            acc[a][0] *= f;
            acc[a][1] *= f;
        }
        __syncthreads();                                   // (D)

        // denom update (reads exp'd Pt)
        if (t < USEL) {
            float su = 0.f;
            for (int k = 0; k < 64; k++) su += Pt[t * 64 + k];
            s_l[t] = s_l[t] * s_f[t] + su;
        }

        // --- acc += P @ V ---
        for (int k = 0; k < 64; k++) {
            float v0 = KV[k * 65 + j];
            float v1 = KV[k * 65 + j + 32];
#pragma unroll
            for (int a = 0; a < 5; a++) {
                float p = Pt[(i + 8 * a) * 64 + k];
                acc[a][0] = fmaf(p, v0, acc[a][0]);
                acc[a][1] = fmaf(p, v1, acc[a][1]);
            }
        }
        __syncthreads();                                   // (E)
    }

    // write partials
    float* pa = g_pacc + (size_t)(bh * NCH + ch) * USEL * DIM;
#pragma unroll
    for (int a = 0; a < 5; a++) {
        int q = i + 8 * a;
        pa[q * DIM + j]      = acc[a][0];
        pa[q * DIM + j + 32] = acc[a][1];
    }
    if (t < USEL) {
        g_pm[(bh * NCH + ch) * USEL + t] = s_m[t];
        g_pl[(bh * NCH + ch) * USEL + t] = s_l[t];
    }
}

// ================= 6. merge partials, scatter into output =================
__global__ void merge_kernel(float* __restrict__ out) {
    int u = blockIdx.x, bh = blockIdx.y, d = threadIdx.x;
    float M = -1e30f;
#pragma unroll
    for (int c = 0; c < NCH; c++)
        M = fmaxf(M, g_pm[(bh * NCH + c) * USEL + u]);
    float L = 0.f, o = 0.f;
#pragma unroll
    for (int c = 0; c < NCH; c++) {
        float w = __expf(g_pm[(bh * NCH + c) * USEL + u] - M);
        L += g_pl[(bh * NCH + c) * USEL + u] * w;
        o = fmaf(g_pacc[((size_t)(bh * NCH + c) * USEL + u) * DIM + d], w, o);
    }
    int qi = g_topk[bh * USEL + u];
    out[((size_t)bh * LSEQ + qi) * DIM + d] = o / L;
}

// ================= launcher =================
extern "C" void kernel_launch(void* const* d_in, const int* in_sizes, int n_in,
                              void* d_out, int out_size) {
    const float* Q    = (const float*)d_in[0];
    const float* K    = (const float*)d_in[1];
    const float* V    = (const float*)d_in[2];
    const int*   idxs = (const int*)d_in[3];
    float* out = (float*)d_out;
    int u = in_sizes[3] / LSEQ;   // 40

    mean_kernel<<<BH, 256>>>(V);
    fill_kernel<<<(BH * LSEQ * 16) / 256, 256>>>((float4*)out);
    m_kernel<<<BH * LSEQ / 8, 256>>>(Q, K, idxs, u);
    topk_kernel<<<BH, 256>>>();
    attn_kernel<<<dim3(NCH, BH), 256>>>(Q, K, V);
    merge_kernel<<<dim3(USEL, BH), 64>>>(out);
}